// round 15
// baseline (speedup 1.0000x reference)
#include <cuda_runtime.h>
#include <cuda_fp16.h>
#include <stdint.h>
#include <math.h>

#define BATCH 8
#define TLEN  512
#define CINT  512
#define CCONT 192
#define CSPK  256
#define DMLP  1536
#define NWIN  1024
#define FRAME 960
#define LTOT  (TLEN*FRAME)
#define KOUT  3584
#define NW1   (6*DMLP*CINT)

// ---------------- scratch (device globals; t-major activations [B][T][C]) ----------------
__device__ __align__(256) float  d_x[BATCH*TLEN*CINT];
__device__ __align__(256) __half d_h2[BATCH*TLEN*CINT];
__device__ __align__(256) __half d_g2[BATCH*TLEN*DMLP];
__device__ __align__(256) __half d_w1h[NW1];
__device__ __align__(256) __half d_w2h[NW1];
__device__ __align__(256) __half d_wOh[NWIN*KOUT];
__device__ __align__(256) float  d_filt[BATCH*TLEN*NWIN];
__device__ float d_spkadd[BATCH*CINT];

// ---------------- helpers ----------------
__device__ __forceinline__ uint32_t pkh2(float lo, float hi) {
    uint32_t r;
    asm("cvt.rn.f16x2.f32 %0, %1, %2;" : "=r"(r) : "f"(hi), "f"(lo));
    return r;
}
__device__ __forceinline__ void mma_f16(float c[4], const uint32_t a[4], const uint32_t b[2]) {
    asm volatile("mma.sync.aligned.m16n8k16.row.col.f32.f16.f16.f32 "
                 "{%0,%1,%2,%3},{%4,%5,%6,%7},{%8,%9},{%0,%1,%2,%3};"
                 : "+f"(c[0]), "+f"(c[1]), "+f"(c[2]), "+f"(c[3])
                 : "r"(a[0]), "r"(a[1]), "r"(a[2]), "r"(a[3]), "r"(b[0]), "r"(b[1]));
}
__device__ __forceinline__ void ldsm4(uint32_t* r, uint32_t addr) {
    asm volatile("ldmatrix.sync.aligned.m8n8.x4.shared.b16 {%0,%1,%2,%3}, [%4];"
                 : "=r"(r[0]), "=r"(r[1]), "=r"(r[2]), "=r"(r[3]) : "r"(addr));
}
__device__ __forceinline__ float gelu_exact(float v) {
    return 0.5f*v*(1.f + erff(v*0.70710678118654752f));
}
__device__ __forceinline__ void fma2(unsigned long long& acc, unsigned long long a,
                                     unsigned long long b) {
    asm("fma.rn.f32x2 %0, %1, %2, %0;" : "+l"(acc) : "l"(a), "l"(b));
}
__device__ __forceinline__ void upk2(float& lo, float& hi, unsigned long long v) {
    asm("mov.b64 {%0, %1}, %2;" : "=f"(lo), "=f"(hi) : "l"(v));
}
__device__ __forceinline__ uint32_t smem_u32(const void* p) {
    return (uint32_t)__cvta_generic_to_shared(p);
}

// ---------------- prep: all weight conversions in ONE launch ----------------
#define CVT_B1 (NW1/1024)
__global__ void cvtall_kernel(const float* __restrict__ pw1_w,
                              const float* __restrict__ pw2_w,
                              const float* __restrict__ w_out) {
    int blk = blockIdx.x;
    if (blk < 2*CVT_B1) {
        const float* s = (blk < CVT_B1) ? pw1_w : pw2_w;
        __half* d = (blk < CVT_B1) ? d_w1h : d_w2h;
        int base = (blk < CVT_B1) ? blk : blk - CVT_B1;
        size_t i = ((size_t)base*256 + threadIdx.x)*4;
        float4 v = *(const float4*)(s + i);
        uint2 o;
        o.x = pkh2(v.x, v.y);
        o.y = pkh2(v.z, v.w);
        *(uint2*)(d + i) = o;
    } else {
        int idx = (blk - 2*CVT_B1)*256 + threadIdx.x;
        int w = idx / KOUT;
        int r = idx - w*KOUT;
        int kap = r >> 9, c = r & 511;
        d_wOh[idx] = __float2half(w_out[((size_t)w*CINT + c)*7 + kap]);
    }
}

// ---------------- spk matvec + bias fold ----------------
__global__ void spk_kernel(const float* __restrict__ w_spk, const float* __restrict__ spk,
                           const float* __restrict__ b_content, const float* __restrict__ b_spk,
                           const float* __restrict__ b_f0, const float* __restrict__ b_energy) {
    int b = blockIdx.x, o = threadIdx.x;
    __shared__ float sv[CSPK];
    if (o < CSPK) sv[o] = spk[b*CSPK + o];
    __syncthreads();
    float acc = 0.f;
    const float* wr = w_spk + (size_t)o*CSPK;
    #pragma unroll 4
    for (int c = 0; c < CSPK; c++) acc += wr[c]*sv[c];
    d_spkadd[b*CINT + o] = acc + b_content[o] + b_spk[o] + b_f0[o] + b_energy[o];
}

// ---------------- trunk GEMM (FFMA fp32), writes d_x t-major ----------------
__global__ void __launch_bounds__(256) gemm_trunk(
    const float* __restrict__ W, const float* __restrict__ content,
    const float* __restrict__ f0, const float* __restrict__ energy,
    const float* __restrict__ wf0, const float* __restrict__ wen) {
    __shared__ float As[8][128];
    __shared__ float Bs[8][128];
    const int tid = threadIdx.x, b = blockIdx.z;
    const int m0 = blockIdx.x*128, t0 = blockIdx.y*128;
    const int tx = tid & 15, ty = tid >> 4;
    const int am = tid >> 1, ak = (tid & 1)*4;
    const int bk = tid >> 5, bn = (tid & 31)*4;
    float acc[8][8];
    #pragma unroll
    for (int i = 0; i < 8; i++)
        #pragma unroll
        for (int j = 0; j < 8; j++) acc[i][j] = 0.f;
    for (int k0 = 0; k0 < CCONT; k0 += 8) {
        float4 av = *(const float4*)(W + (size_t)(m0+am)*CCONT + k0 + ak);
        As[ak+0][am]=av.x; As[ak+1][am]=av.y; As[ak+2][am]=av.z; As[ak+3][am]=av.w;
        float4 bv = *(const float4*)(content + ((size_t)b*CCONT + k0 + bk)*TLEN + t0 + bn);
        *(float4*)&Bs[bk][bn] = bv;
        __syncthreads();
        #pragma unroll
        for (int kk = 0; kk < 8; kk++) {
            float a[8], bb[8];
            #pragma unroll
            for (int i = 0; i < 8; i++) a[i] = As[kk][ty*8+i];
            #pragma unroll
            for (int j = 0; j < 8; j++) bb[j] = Bs[kk][tx*8+j];
            #pragma unroll
            for (int i = 0; i < 8; i++)
                #pragma unroll
                for (int j = 0; j < 8; j++) acc[i][j] += a[i]*bb[j];
        }
        __syncthreads();
    }
    float lf[8], en[8];
    #pragma unroll
    for (int j = 0; j < 8; j++) {
        int t = t0 + tx*8 + j;
        float f = f0[b*TLEN + t];
        lf[j] = logf(fmaxf(f, 0.f) + 1e-6f);
        en[j] = energy[b*TLEN + t];
    }
    #pragma unroll
    for (int i = 0; i < 8; i++) {
        int m = m0 + ty*8 + i;
        float base = d_spkadd[b*CINT + m];
        float wf = wf0[m], we = wen[m];
        #pragma unroll
        for (int j = 0; j < 8; j++) {
            int t = t0 + tx*8 + j;
            d_x[((size_t)b*TLEN + t)*CINT + m] = acc[i][j] + base + wf*lf[j] + we*en[j];
        }
    }
}

// ---------------- fused dwconv(k=7,zero-pad) + LN stats + normalize -> half2 ----------------
template<bool DW>
__global__ void __launch_bounds__(256) dwstats(const float* __restrict__ dww,
                                               const float* __restrict__ dwb,
                                               const float* __restrict__ lng,
                                               const float* __restrict__ lnb) {
    const int b = blockIdx.y;
    const int t0 = blockIdx.x * 8;
    const int tid = threadIdx.x;
    const int c0 = 2*tid;
    __shared__ float ssum[8][256];
    __shared__ float ssq[8][256];

    float h[8][2];
    if (DW) {
        float2 wv[7];
        #pragma unroll
        for (int k = 0; k < 7; k++) {
            wv[k].x = dww[c0*7 + k];
            wv[k].y = dww[(c0+1)*7 + k];
        }
        float bx = dwb[c0], by = dwb[c0+1];
        float2 xv[14];
        #pragma unroll
        for (int j = 0; j < 14; j++) {
            int row = t0 + j - 3;
            if (row >= 0 && row < TLEN)
                xv[j] = *(const float2*)(d_x + ((size_t)b*TLEN + row)*CINT + c0);
            else
                xv[j] = make_float2(0.f, 0.f);
        }
        #pragma unroll
        for (int j = 0; j < 8; j++) {
            float a = bx, c = by;
            #pragma unroll
            for (int k = 0; k < 7; k++) {
                a += wv[k].x * xv[j+k].x;
                c += wv[k].y * xv[j+k].y;
            }
            h[j][0] = a; h[j][1] = c;
        }
    } else {
        #pragma unroll
        for (int j = 0; j < 8; j++) {
            float2 v = *(const float2*)(d_x + ((size_t)b*TLEN + t0 + j)*CINT + c0);
            h[j][0] = v.x; h[j][1] = v.y;
        }
    }

    #pragma unroll
    for (int j = 0; j < 8; j++) {
        ssum[j][tid] = h[j][0] + h[j][1];
        ssq[j][tid]  = h[j][0]*h[j][0] + h[j][1]*h[j][1];
    }
    __syncthreads();
    for (int step = 128; step > 0; step >>= 1) {
        if (tid < step) {
            #pragma unroll
            for (int j = 0; j < 8; j++) {
                ssum[j][tid] += ssum[j][tid+step];
                ssq[j][tid]  += ssq[j][tid+step];
            }
        }
        __syncthreads();
    }
    float g0 = lng[c0], g1 = lng[c0+1];
    float b0 = lnb[c0], b1 = lnb[c0+1];
    #pragma unroll
    for (int j = 0; j < 8; j++) {
        float mu = ssum[j][0] * (1.f/CINT);
        float rs = rsqrtf(ssq[j][0] * (1.f/CINT) - mu*mu + 1e-6f);
        float lo = (h[j][0]-mu)*rs*g0 + b0;
        float hi = (h[j][1]-mu)*rs*g1 + b1;
        *(uint32_t*)&d_h2[((size_t)b*TLEN + t0 + j)*CINT + c0] = pkh2(lo, hi);
    }
}

// ==================================================================
// fp16 m16n8k16 GEMM: 128x128 tile, BK=32, double-buffered, 2 CTAs/SM,
// ldmatrix fragment loads from padded row-major smem (80B rows,
// slot = (5*row + c) mod 8 => conflict-free LDSM and STS).
// MODE 0: pw1 (K=CINT,  epi gelu+bias -> d_g2 half)
// MODE 1: pw2 (K=DMLP,  epi +bias+residual -> d_x fp32)
// MODE 2: out (K=KOUT,  A=im2col(d_h2) clamp, epi +bias -> d_filt fp32)
// ==================================================================
#define STAGE_BYTES (128*80)

#define G_LOAD(K0) { \
    const __half* ap_; \
    if (MODE == 2) { \
        int kap = (K0) >> 9; \
        int te = t0 + row + kap - 3; \
        te = te < 0 ? 0 : (te > TLEN-1 ? TLEN-1 : te); \
        ap_ = Aact + ((size_t)bb*TLEN + te)*CINT + (((K0) & 511) + ch); \
    } else { \
        ap_ = Aact + ((size_t)bb*TLEN + t0 + row)*ROWL + (K0) + ch; \
    } \
    ra0 = *(const uint4*)ap_; \
    ra1 = *(const uint4*)(ap_ + 8); \
    const __half* bp_ = Wh + (size_t)(n0+row)*KTOT + (K0) + ch; \
    rb0 = *(const uint4*)bp_; \
    rb1 = *(const uint4*)(bp_ + 8); }

#define G_STORE(S) { \
    *(uint4*)&Ah[S][row][ch]   = ra0; \
    *(uint4*)&Ah[S][row][ch+8] = ra1; \
    *(uint4*)&Bh[S][row][ch]   = rb0; \
    *(uint4*)&Bh[S][row][ch+8] = rb1; }

#define GEMM_COMPUTE(S, KH) { \
    uint32_t afr[4][4], bfr[4][2], btmp[4]; \
    _Pragma("unroll") \
    for (int mf = 0; mf < 4; mf++) \
        ldsm4(afr[mf], aAddr + (S)*STAGE_BYTES + (KH)*32 + mf*1280); \
    ldsm4(btmp, bAddr + (S)*STAGE_BYTES + (KH)*32); \
    bfr[0][0]=btmp[0]; bfr[0][1]=btmp[1]; bfr[1][0]=btmp[2]; bfr[1][1]=btmp[3]; \
    ldsm4(btmp, bAddr + (S)*STAGE_BYTES + (KH)*32 + 1280); \
    bfr[2][0]=btmp[0]; bfr[2][1]=btmp[1]; bfr[3][0]=btmp[2]; bfr[3][1]=btmp[3]; \
    _Pragma("unroll") \
    for (int mf=0;mf<4;mf++) \
        _Pragma("unroll") \
        for (int nf=0;nf<4;nf++) \
            mma_f16(acc[mf][nf], afr[mf], bfr[nf]); }

template<int KTOT, int MODE>
__global__ void __launch_bounds__(256, 2) gemm5(const __half* __restrict__ Aact,
                                                const __half* __restrict__ Wh,
                                                const float* __restrict__ bias) {
    __shared__ __align__(16) __half Ah[2][128][40];
    __shared__ __align__(16) __half Bh[2][128][40];
    const int tid = threadIdx.x;
    const int bb = blockIdx.z;
    const int t0 = blockIdx.x * 128;
    const int n0 = blockIdx.y * 128;
    const int warp = tid >> 5, lane = tid & 31;
    const int wm = (warp >> 2) * 64, wn = (warp & 3) * 32;
    const int g = lane >> 2, tg = lane & 3;
    const int row = tid & 127;
    const int ch  = (tid >> 7) * 16;      // half offset within 32-K stage
    constexpr int ROWL = (MODE == 1) ? DMLP : CINT;

    // ldmatrix lane addresses (bytes, stage-0 base)
    const int mat = lane >> 3, r8 = lane & 7;
    const uint32_t aAddr = smem_u32(&Ah[0][0][0])
        + (uint32_t)((wm + (mat & 1)*8 + r8)*80 + (mat >> 1)*16);
    const uint32_t bAddr = smem_u32(&Bh[0][0][0])
        + (uint32_t)((wn + (mat >> 1)*8 + r8)*80 + (mat & 1)*16);

    float acc[4][4][4];
    #pragma unroll
    for (int i=0;i<4;i++)
        #pragma unroll
        for (int j=0;j<4;j++)
            #pragma unroll
            for (int k=0;k<4;k++) acc[i][j][k]=0.f;

    uint4 ra0, ra1, rb0, rb1;
    G_LOAD(0)
    G_STORE(0)
    __syncthreads();
    int buf = 0;
    #pragma unroll 1
    for (int k0 = 32; k0 < KTOT; k0 += 32) {
        G_LOAD(k0)
        GEMM_COMPUTE(buf, 0)
        GEMM_COMPUTE(buf, 1)
        G_STORE(buf^1)
        __syncthreads();
        buf ^= 1;
    }
    GEMM_COMPUTE(buf, 0)
    GEMM_COMPUTE(buf, 1)

    #pragma unroll
    for (int mf=0;mf<4;mf++) {
        int t = t0 + wm + mf*16 + g;
        #pragma unroll
        for (int nf=0;nf<4;nf++) {
            int n = n0 + wn + nf*8 + 2*tg;
            float2 bi = *(const float2*)(bias + n);
            float v00 = acc[mf][nf][0] + bi.x;
            float v01 = acc[mf][nf][1] + bi.y;
            float v10 = acc[mf][nf][2] + bi.x;
            float v11 = acc[mf][nf][3] + bi.y;
            if (MODE == 0) {
                v00 = gelu_exact(v00); v01 = gelu_exact(v01);
                v10 = gelu_exact(v10); v11 = gelu_exact(v11);
                *(uint32_t*)&d_g2[((size_t)bb*TLEN + t  )*DMLP + n] = pkh2(v00, v01);
                *(uint32_t*)&d_g2[((size_t)bb*TLEN + t+8)*DMLP + n] = pkh2(v10, v11);
            } else if (MODE == 1) {
                float* p0 = d_x + ((size_t)bb*TLEN + t  )*CINT + n;
                float* p1 = d_x + ((size_t)bb*TLEN + t+8)*CINT + n;
                float2 r0 = *(float2*)p0;
                float2 r1 = *(float2*)p1;
                r0.x += v00; r0.y += v01;
                r1.x += v10; r1.y += v11;
                *(float2*)p0 = r0;
                *(float2*)p1 = r1;
            } else {
                *(float2*)(d_filt + ((size_t)bb*TLEN + t  )*NWIN + n) = make_float2(v00, v01);
                *(float2*)(d_filt + ((size_t)bb*TLEN + t+8)*NWIN + n) = make_float2(v10, v11);
            }
        }
    }
}

// ---------------- zero output ----------------
__global__ void zero_kernel(float* __restrict__ out) {
    size_t i = ((size_t)blockIdx.x*256 + threadIdx.x)*4;
    *(float4*)(out + i) = make_float4(0.f,0.f,0.f,0.f);
}

// ---------------- per-frame FIR + overlap-add: sliding-window registers ----------------
__global__ void __launch_bounds__(256) fir5_kernel(const float* __restrict__ src,
                                                   float* __restrict__ out) {
    const int f = blockIdx.x, b = blockIdx.y;
    __shared__ __align__(16) float2 s_fk[1024];
    __shared__ __align__(16) float2 s_even[1544];
    __shared__ __align__(16) float2 s_odd[1544];
    const int tid = threadIdx.x;
    const float* sb = src + (size_t)b*LTOT + (size_t)f*FRAME;

    for (int j = tid; j < 1536; j += 256) {
        int i0 = 2*j - 1024;
        float a = (i0   >= 0 && i0   < FRAME) ? sb[i0]   : 0.f;
        float m = (i0+1 >= 0 && i0+1 < FRAME) ? sb[i0+1] : 0.f;
        float c = (i0+2 >= 0 && i0+2 < FRAME) ? sb[i0+2] : 0.f;
        s_even[j] = make_float2(a, m);
        s_odd[j]  = make_float2(m, c);
    }
    for (int k = tid; k < 1024; k += 256) {
        float fv = d_filt[((size_t)(b*TLEN + f))*NWIN + k];
        s_fk[k] = make_float2(fv, fv);
    }
    __syncthreads();

    if (tid >= 248) return;
    const int j0 = tid*8;
    unsigned long long accp[4] = {0ull, 0ull, 0ull, 0ull};
    const ulonglong2* FK = (const ulonglong2*)s_fk;
    const ulonglong2* EV2 = (const ulonglong2*)s_even + 2*tid;
    const ulonglong2* OD2 = (const ulonglong2*)s_odd + 2*tid;

    unsigned long long A[12], B[12];
    #pragma unroll
    for (int i = 0; i < 6; i++) {
        ulonglong2 va = EV2[i];
        A[2*i] = va.x; A[2*i+1] = va.y;
        ulonglong2 vb = OD2[i];
        B[2*i] = vb.x; B[2*i+1] = vb.y;
    }
    int ldoff = 6;

    #pragma unroll 1
    for (int kc = 0; kc < 1024; kc += 16) {
        const int fk2 = kc >> 1;
        {
            ulonglong2 f0 = FK[fk2+0], f1 = FK[fk2+1], f2 = FK[fk2+2], f3 = FK[fk2+3];
            unsigned long long fkp[8] = {f0.x,f0.y,f1.x,f1.y,f2.x,f2.y,f3.x,f3.y};
            #pragma unroll
            for (int q = 0; q < 8; q += 2) {
                #pragma unroll
                for (int r2 = 0; r2 < 4; r2++) fma2(accp[r2], fkp[q],   A[q/2 + r2]);
                #pragma unroll
                for (int r2 = 0; r2 < 4; r2++) fma2(accp[r2], fkp[q+1], B[q/2 + r2]);
            }
        }
        unsigned long long NA[8], NB[8];
        const bool more = (kc + 16) < 1024;
        if (more) {
            #pragma unroll
            for (int i = 0; i < 4; i++) {
                ulonglong2 va = EV2[ldoff + i];
                NA[2*i] = va.x; NA[2*i+1] = va.y;
                ulonglong2 vb = OD2[ldoff + i];
                NB[2*i] = vb.x; NB[2*i+1] = vb.y;
            }
        }
        {
            ulonglong2 f0 = FK[fk2+4], f1 = FK[fk2+5], f2 = FK[fk2+6], f3 = FK[fk2+7];
            unsigned long long fkp[8] = {f0.x,f0.y,f1.x,f1.y,f2.x,f2.y,f3.x,f3.y};
            #pragma unroll
            for (int q = 0; q < 8; q += 2) {
                #pragma unroll
                for (int r2 = 0; r2 < 4; r2++) fma2(accp[r2], fkp[q],   A[4 + q/2 + r2]);
                #pragma unroll
                for (int r2 = 0; r2 < 4; r2++) fma2(accp[r2], fkp[q+1], B[4 + q/2 + r2]);
            }
        }
        if (more) {
            #pragma unroll
            for (int i = 0; i < 4; i++) { A[i] = A[8+i]; B[i] = B[8+i]; }
            #pragma unroll
            for (int i = 0; i < 8; i++) { A[4+i] = NA[i]; B[4+i] = NB[i]; }
            ldoff += 4;
        }
    }

    float accf[8];
    #pragma unroll
    for (int r2 = 0; r2 < 4; r2++) upk2(accf[2*r2], accf[2*r2+1], accp[r2]);
    const int u0 = f*FRAME + j0;
    #pragma unroll
    for (int r = 0; r < 8; r++) {
        int j = j0 + r, u = u0 + r;
        if (j >= 1 && u < LTOT)
            atomicAdd(out + (size_t)b*LTOT + u, accf[r]);
    }
}

// ---------------- host launcher ----------------
extern "C" void kernel_launch(void* const* d_in, const int* in_sizes, int n_in,
                              void* d_out, int out_size) {
    const float* content  = (const float*)d_in[0];
    const float* f0       = (const float*)d_in[1];
    const float* energy   = (const float*)d_in[2];
    const float* spk      = (const float*)d_in[3];
    const float* source   = (const float*)d_in[4];
    const float* w_content= (const float*)d_in[5];
    const float* b_content= (const float*)d_in[6];
    const float* w_spk    = (const float*)d_in[7];
    const float* b_spk    = (const float*)d_in[8];
    const float* w_f0     = (const float*)d_in[9];
    const float* b_f0     = (const float*)d_in[10];
    const float* w_energy = (const float*)d_in[11];
    const float* b_energy = (const float*)d_in[12];
    const float* dw_w     = (const float*)d_in[13];
    const float* dw_b     = (const float*)d_in[14];
    const float* ln_g     = (const float*)d_in[15];
    const float* ln_b     = (const float*)d_in[16];
    const float* pw1_w    = (const float*)d_in[17];
    const float* pw1_b    = (const float*)d_in[18];
    const float* pw2_w    = (const float*)d_in[19];
    const float* pw2_b    = (const float*)d_in[20];
    const float* out_ln_g = (const float*)d_in[21];
    const float* out_ln_b = (const float*)d_in[22];
    const float* w_out    = (const float*)d_in[23];
    const float* b_out    = (const float*)d_in[24];
    float* out = (float*)d_out;

    __half *w1h, *w2h, *wOh, *h2g, *g2g;
    cudaGetSymbolAddress((void**)&w1h, d_w1h);
    cudaGetSymbolAddress((void**)&w2h, d_w2h);
    cudaGetSymbolAddress((void**)&wOh, d_wOh);
    cudaGetSymbolAddress((void**)&h2g, d_h2);
    cudaGetSymbolAddress((void**)&g2g, d_g2);

    zero_kernel<<<BATCH*LTOT/1024, 256>>>(out);
    cvtall_kernel<<<2*CVT_B1 + NWIN*KOUT/256, 256>>>(pw1_w, pw2_w, w_out);
    spk_kernel<<<BATCH, 512>>>(w_spk, spk, b_content, b_spk, b_f0, b_energy);
    gemm_trunk<<<dim3(CINT/128, TLEN/128, BATCH), 256>>>(w_content, content, f0,
                                                         energy, w_f0, w_energy);
    for (int l = 0; l < 6; l++) {
        dwstats<true><<<dim3(TLEN/8, BATCH), 256>>>(dw_w + (size_t)l*CINT*7,
                                                    dw_b + (size_t)l*CINT,
                                                    ln_g + (size_t)l*CINT,
                                                    ln_b + (size_t)l*CINT);
        gemm5<CINT,0><<<dim3(4, DMLP/128, BATCH), 256>>>(
            h2g, w1h + (size_t)l*DMLP*CINT, pw1_b + (size_t)l*DMLP);
        gemm5<DMLP,1><<<dim3(4, CINT/128, BATCH), 256>>>(
            g2g, w2h + (size_t)l*CINT*DMLP, pw2_b + (size_t)l*CINT);
    }
    dwstats<false><<<dim3(TLEN/8, BATCH), 256>>>(nullptr, nullptr, out_ln_g, out_ln_b);
    gemm5<KOUT,2><<<dim3(4, NWIN/128, BATCH), 256>>>(h2g, wOh, b_out);
    fir5_kernel<<<dim3(TLEN, BATCH), 256>>>(source, out);
}

// round 16
// speedup vs baseline: 1.1110x; 1.1110x over previous
#include <cuda_runtime.h>
#include <cuda_fp16.h>
#include <stdint.h>
#include <math.h>

#define BATCH 8
#define TLEN  512
#define CINT  512
#define CCONT 192
#define CSPK  256
#define DMLP  1536
#define NWIN  1024
#define FRAME 960
#define LTOT  (TLEN*FRAME)
#define KOUT  3584
#define NW1   (6*DMLP*CINT)

// ---------------- scratch (device globals; t-major activations [B][T][C]) ----------------
__device__ __align__(256) float  d_x[BATCH*TLEN*CINT];
__device__ __align__(256) __half d_h2[BATCH*TLEN*CINT];
__device__ __align__(256) __half d_g2[BATCH*TLEN*DMLP];
__device__ __align__(256) __half d_w1h[NW1];
__device__ __align__(256) __half d_w2h[NW1];
__device__ __align__(256) __half d_wOh[NWIN*KOUT];
__device__ __align__(256) float  d_filt[BATCH*TLEN*NWIN];
__device__ float d_spkadd[BATCH*CINT];

// ---------------- helpers ----------------
__device__ __forceinline__ uint32_t pkh2(float lo, float hi) {
    uint32_t r;
    asm("cvt.rn.f16x2.f32 %0, %1, %2;" : "=r"(r) : "f"(hi), "f"(lo));
    return r;
}
__device__ __forceinline__ void mma_f16(float c[4], const uint32_t a[4], const uint32_t b[2]) {
    asm volatile("mma.sync.aligned.m16n8k16.row.col.f32.f16.f16.f32 "
                 "{%0,%1,%2,%3},{%4,%5,%6,%7},{%8,%9},{%0,%1,%2,%3};"
                 : "+f"(c[0]), "+f"(c[1]), "+f"(c[2]), "+f"(c[3])
                 : "r"(a[0]), "r"(a[1]), "r"(a[2]), "r"(a[3]), "r"(b[0]), "r"(b[1]));
}
__device__ __forceinline__ float gelu_exact(float v) {
    return 0.5f*v*(1.f + erff(v*0.70710678118654752f));
}
__device__ __forceinline__ void fma2(unsigned long long& acc, unsigned long long a,
                                     unsigned long long b) {
    asm("fma.rn.f32x2 %0, %1, %2, %0;" : "+l"(acc) : "l"(a), "l"(b));
}
__device__ __forceinline__ void upk2(float& lo, float& hi, unsigned long long v) {
    asm("mov.b64 {%0, %1}, %2;" : "=f"(lo), "=f"(hi) : "l"(v));
}

// ---------------- prep: all weight conversions in ONE launch ----------------
#define CVT_B1 (NW1/1024)
__global__ void cvtall_kernel(const float* __restrict__ pw1_w,
                              const float* __restrict__ pw2_w,
                              const float* __restrict__ w_out) {
    int blk = blockIdx.x;
    if (blk < 2*CVT_B1) {
        const float* s = (blk < CVT_B1) ? pw1_w : pw2_w;
        __half* d = (blk < CVT_B1) ? d_w1h : d_w2h;
        int base = (blk < CVT_B1) ? blk : blk - CVT_B1;
        size_t i = ((size_t)base*256 + threadIdx.x)*4;
        float4 v = *(const float4*)(s + i);
        uint2 o;
        o.x = pkh2(v.x, v.y);
        o.y = pkh2(v.z, v.w);
        *(uint2*)(d + i) = o;
    } else {
        int idx = (blk - 2*CVT_B1)*256 + threadIdx.x;
        int w = idx / KOUT;
        int r = idx - w*KOUT;
        int kap = r >> 9, c = r & 511;
        d_wOh[idx] = __float2half(w_out[((size_t)w*CINT + c)*7 + kap]);
    }
}

// ---------------- spk matvec + bias fold ----------------
__global__ void spk_kernel(const float* __restrict__ w_spk, const float* __restrict__ spk,
                           const float* __restrict__ b_content, const float* __restrict__ b_spk,
                           const float* __restrict__ b_f0, const float* __restrict__ b_energy) {
    int b = blockIdx.x, o = threadIdx.x;
    __shared__ float sv[CSPK];
    if (o < CSPK) sv[o] = spk[b*CSPK + o];
    __syncthreads();
    float acc = 0.f;
    const float* wr = w_spk + (size_t)o*CSPK;
    #pragma unroll 4
    for (int c = 0; c < CSPK; c++) acc += wr[c]*sv[c];
    d_spkadd[b*CINT + o] = acc + b_content[o] + b_spk[o] + b_f0[o] + b_energy[o];
}

// ---------------- trunk GEMM (FFMA fp32), writes d_x t-major; 2 CTAs/SM ----------------
__global__ void __launch_bounds__(256, 2) gemm_trunk(
    const float* __restrict__ W, const float* __restrict__ content,
    const float* __restrict__ f0, const float* __restrict__ energy,
    const float* __restrict__ wf0, const float* __restrict__ wen) {
    __shared__ float As[8][128];
    __shared__ float Bs[8][128];
    const int tid = threadIdx.x, b = blockIdx.z;
    const int m0 = blockIdx.x*128, t0 = blockIdx.y*128;
    const int tx = tid & 15, ty = tid >> 4;
    const int am = tid >> 1, ak = (tid & 1)*4;
    const int bk = tid >> 5, bn = (tid & 31)*4;
    float acc[8][8];
    #pragma unroll
    for (int i = 0; i < 8; i++)
        #pragma unroll
        for (int j = 0; j < 8; j++) acc[i][j] = 0.f;
    for (int k0 = 0; k0 < CCONT; k0 += 8) {
        float4 av = *(const float4*)(W + (size_t)(m0+am)*CCONT + k0 + ak);
        As[ak+0][am]=av.x; As[ak+1][am]=av.y; As[ak+2][am]=av.z; As[ak+3][am]=av.w;
        float4 bv = *(const float4*)(content + ((size_t)b*CCONT + k0 + bk)*TLEN + t0 + bn);
        *(float4*)&Bs[bk][bn] = bv;
        __syncthreads();
        #pragma unroll
        for (int kk = 0; kk < 8; kk++) {
            float a[8], bb[8];
            #pragma unroll
            for (int i = 0; i < 8; i++) a[i] = As[kk][ty*8+i];
            #pragma unroll
            for (int j = 0; j < 8; j++) bb[j] = Bs[kk][tx*8+j];
            #pragma unroll
            for (int i = 0; i < 8; i++)
                #pragma unroll
                for (int j = 0; j < 8; j++) acc[i][j] += a[i]*bb[j];
        }
        __syncthreads();
    }
    float lf[8], en[8];
    #pragma unroll
    for (int j = 0; j < 8; j++) {
        int t = t0 + tx*8 + j;
        float f = f0[b*TLEN + t];
        lf[j] = logf(fmaxf(f, 0.f) + 1e-6f);
        en[j] = energy[b*TLEN + t];
    }
    #pragma unroll
    for (int i = 0; i < 8; i++) {
        int m = m0 + ty*8 + i;
        float base = d_spkadd[b*CINT + m];
        float wf = wf0[m], we = wen[m];
        #pragma unroll
        for (int j = 0; j < 8; j++) {
            int t = t0 + tx*8 + j;
            d_x[((size_t)b*TLEN + t)*CINT + m] = acc[i][j] + base + wf*lf[j] + we*en[j];
        }
    }
}

// ---------------- fused dwconv(k=7,zero-pad) + LN stats + normalize -> half2 ----------------
template<bool DW>
__global__ void __launch_bounds__(256) dwstats(const float* __restrict__ dww,
                                               const float* __restrict__ dwb,
                                               const float* __restrict__ lng,
                                               const float* __restrict__ lnb) {
    const int b = blockIdx.y;
    const int t0 = blockIdx.x * 8;
    const int tid = threadIdx.x;
    const int c0 = 2*tid;
    __shared__ float ssum[8][256];
    __shared__ float ssq[8][256];

    float h[8][2];
    if (DW) {
        float2 wv[7];
        #pragma unroll
        for (int k = 0; k < 7; k++) {
            wv[k].x = dww[c0*7 + k];
            wv[k].y = dww[(c0+1)*7 + k];
        }
        float bx = dwb[c0], by = dwb[c0+1];
        float2 xv[14];
        #pragma unroll
        for (int j = 0; j < 14; j++) {
            int row = t0 + j - 3;
            if (row >= 0 && row < TLEN)
                xv[j] = *(const float2*)(d_x + ((size_t)b*TLEN + row)*CINT + c0);
            else
                xv[j] = make_float2(0.f, 0.f);
        }
        #pragma unroll
        for (int j = 0; j < 8; j++) {
            float a = bx, c = by;
            #pragma unroll
            for (int k = 0; k < 7; k++) {
                a += wv[k].x * xv[j+k].x;
                c += wv[k].y * xv[j+k].y;
            }
            h[j][0] = a; h[j][1] = c;
        }
    } else {
        #pragma unroll
        for (int j = 0; j < 8; j++) {
            float2 v = *(const float2*)(d_x + ((size_t)b*TLEN + t0 + j)*CINT + c0);
            h[j][0] = v.x; h[j][1] = v.y;
        }
    }

    #pragma unroll
    for (int j = 0; j < 8; j++) {
        ssum[j][tid] = h[j][0] + h[j][1];
        ssq[j][tid]  = h[j][0]*h[j][0] + h[j][1]*h[j][1];
    }
    __syncthreads();
    for (int step = 128; step > 0; step >>= 1) {
        if (tid < step) {
            #pragma unroll
            for (int j = 0; j < 8; j++) {
                ssum[j][tid] += ssum[j][tid+step];
                ssq[j][tid]  += ssq[j][tid+step];
            }
        }
        __syncthreads();
    }
    float g0 = lng[c0], g1 = lng[c0+1];
    float b0 = lnb[c0], b1 = lnb[c0+1];
    #pragma unroll
    for (int j = 0; j < 8; j++) {
        float mu = ssum[j][0] * (1.f/CINT);
        float rs = rsqrtf(ssq[j][0] * (1.f/CINT) - mu*mu + 1e-6f);
        float lo = (h[j][0]-mu)*rs*g0 + b0;
        float hi = (h[j][1]-mu)*rs*g1 + b1;
        *(uint32_t*)&d_h2[((size_t)b*TLEN + t0 + j)*CINT + c0] = pkh2(lo, hi);
    }
}

// ==================================================================
// fp16 m16n8k16 GEMM: 128x128 tile, BK=32, double-buffered, 2 CTAs/SM.
// (R13 proven structure; unroll 2 lets ptxas schedule across buffers.)
// MODE 0: pw1 (K=CINT,  epi gelu+bias -> d_g2 half)
// MODE 1: pw2 (K=DMLP,  epi +bias+residual -> d_x fp32)
// MODE 2: out (K=KOUT,  A=im2col(d_h2) clamp, epi +bias -> d_filt fp32)
// ==================================================================
#define GEMM_COMPUTE(B_, SUB) { \
    uint32_t afr[4][4], bfr[4][2]; \
    _Pragma("unroll") \
    for (int mf=0; mf<4; mf++) { \
        int m = wm + mf*16 + g; \
        afr[mf][0] = As[B_][8*(SUB)+tg][m]; \
        afr[mf][1] = As[B_][8*(SUB)+tg][m+8]; \
        afr[mf][2] = As[B_][8*(SUB)+tg+4][m]; \
        afr[mf][3] = As[B_][8*(SUB)+tg+4][m+8]; \
    } \
    _Pragma("unroll") \
    for (int nf=0; nf<4; nf++) { \
        int n = wn + nf*8 + g; \
        bfr[nf][0] = Bs[B_][8*(SUB)+tg][n]; \
        bfr[nf][1] = Bs[B_][8*(SUB)+tg+4][n]; \
    } \
    _Pragma("unroll") \
    for (int mf=0;mf<4;mf++) \
        _Pragma("unroll") \
        for (int nf=0;nf<4;nf++) \
            mma_f16(acc[mf][nf], afr[mf], bfr[nf]); }

#define G_LOAD(K0) { \
    const __half* ap_; \
    if (MODE == 2) { \
        int kap = (K0) >> 9; \
        int te = t0 + row + kap - 3; \
        te = te < 0 ? 0 : (te > TLEN-1 ? TLEN-1 : te); \
        ap_ = Aact + ((size_t)bb*TLEN + te)*CINT + (((K0) & 511) + ch); \
    } else { \
        ap_ = Aact + ((size_t)bb*TLEN + t0 + row)*ROWL + (K0) + ch; \
    } \
    ra0 = *(const uint4*)ap_; \
    ra1 = *(const uint4*)(ap_ + 8); \
    const __half* bp_ = Wh + (size_t)(n0+row)*KTOT + (K0) + ch; \
    rb0 = *(const uint4*)bp_; \
    rb1 = *(const uint4*)(bp_ + 8); }

#define G_STORE(S) { \
    As[S][k2o+0][row]=ra0.x; As[S][k2o+1][row]=ra0.y; \
    As[S][k2o+2][row]=ra0.z; As[S][k2o+3][row]=ra0.w; \
    As[S][k2o+4][row]=ra1.x; As[S][k2o+5][row]=ra1.y; \
    As[S][k2o+6][row]=ra1.z; As[S][k2o+7][row]=ra1.w; \
    Bs[S][k2o+0][row]=rb0.x; Bs[S][k2o+1][row]=rb0.y; \
    Bs[S][k2o+2][row]=rb0.z; Bs[S][k2o+3][row]=rb0.w; \
    Bs[S][k2o+4][row]=rb1.x; Bs[S][k2o+5][row]=rb1.y; \
    Bs[S][k2o+6][row]=rb1.z; Bs[S][k2o+7][row]=rb1.w; }

template<int KTOT, int MODE>
__global__ void __launch_bounds__(256, 2) gemm5(const __half* __restrict__ Aact,
                                                const __half* __restrict__ Wh,
                                                const float* __restrict__ bias) {
    __shared__ uint32_t As[2][16][136];
    __shared__ uint32_t Bs[2][16][136];
    const int tid = threadIdx.x;
    const int bb = blockIdx.z;
    const int t0 = blockIdx.x * 128;
    const int n0 = blockIdx.y * 128;
    const int warp = tid >> 5, lane = tid & 31;
    const int wm = (warp >> 2) * 64, wn = (warp & 3) * 32;
    const int g = lane >> 2, tg = lane & 3;
    const int row = tid >> 1;
    const int ch  = (tid & 1) * 16;
    const int k2o = (tid & 1) * 8;
    constexpr int ROWL = (MODE == 1) ? DMLP : CINT;

    float acc[4][4][4];
    #pragma unroll
    for (int i=0;i<4;i++)
        #pragma unroll
        for (int j=0;j<4;j++)
            #pragma unroll
            for (int k=0;k<4;k++) acc[i][j][k]=0.f;

    uint4 ra0, ra1, rb0, rb1;
    G_LOAD(0)
    G_STORE(0)
    __syncthreads();
    int buf = 0;
    #pragma unroll 2
    for (int k0 = 32; k0 < KTOT; k0 += 32) {
        G_LOAD(k0)
        GEMM_COMPUTE(buf, 0)
        GEMM_COMPUTE(buf, 1)
        G_STORE(buf^1)
        __syncthreads();
        buf ^= 1;
    }
    GEMM_COMPUTE(buf, 0)
    GEMM_COMPUTE(buf, 1)

    #pragma unroll
    for (int mf=0;mf<4;mf++) {
        int t = t0 + wm + mf*16 + g;
        #pragma unroll
        for (int nf=0;nf<4;nf++) {
            int n = n0 + wn + nf*8 + 2*tg;
            float2 bi = *(const float2*)(bias + n);
            float v00 = acc[mf][nf][0] + bi.x;
            float v01 = acc[mf][nf][1] + bi.y;
            float v10 = acc[mf][nf][2] + bi.x;
            float v11 = acc[mf][nf][3] + bi.y;
            if (MODE == 0) {
                v00 = gelu_exact(v00); v01 = gelu_exact(v01);
                v10 = gelu_exact(v10); v11 = gelu_exact(v11);
                *(uint32_t*)&d_g2[((size_t)bb*TLEN + t  )*DMLP + n] = pkh2(v00, v01);
                *(uint32_t*)&d_g2[((size_t)bb*TLEN + t+8)*DMLP + n] = pkh2(v10, v11);
            } else if (MODE == 1) {
                float* p0 = d_x + ((size_t)bb*TLEN + t  )*CINT + n;
                float* p1 = d_x + ((size_t)bb*TLEN + t+8)*CINT + n;
                float2 r0 = *(float2*)p0;
                float2 r1 = *(float2*)p1;
                r0.x += v00; r0.y += v01;
                r1.x += v10; r1.y += v11;
                *(float2*)p0 = r0;
                *(float2*)p1 = r1;
            } else {
                *(float2*)(d_filt + ((size_t)bb*TLEN + t  )*NWIN + n) = make_float2(v00, v01);
                *(float2*)(d_filt + ((size_t)bb*TLEN + t+8)*NWIN + n) = make_float2(v10, v11);
            }
        }
    }
}

// ---------------- zero output ----------------
__global__ void zero_kernel(float* __restrict__ out) {
    size_t i = ((size_t)blockIdx.x*256 + threadIdx.x)*4;
    *(float4*)(out + i) = make_float4(0.f,0.f,0.f,0.f);
}

// ---------------- per-frame FIR + overlap-add: sliding-window registers ----------------
__global__ void __launch_bounds__(256) fir5_kernel(const float* __restrict__ src,
                                                   float* __restrict__ out) {
    const int f = blockIdx.x, b = blockIdx.y;
    __shared__ __align__(16) float2 s_fk[1024];
    __shared__ __align__(16) float2 s_even[1544];
    __shared__ __align__(16) float2 s_odd[1544];
    const int tid = threadIdx.x;
    const float* sb = src + (size_t)b*LTOT + (size_t)f*FRAME;

    for (int j = tid; j < 1536; j += 256) {
        int i0 = 2*j - 1024;
        float a = (i0   >= 0 && i0   < FRAME) ? sb[i0]   : 0.f;
        float m = (i0+1 >= 0 && i0+1 < FRAME) ? sb[i0+1] : 0.f;
        float c = (i0+2 >= 0 && i0+2 < FRAME) ? sb[i0+2] : 0.f;
        s_even[j] = make_float2(a, m);
        s_odd[j]  = make_float2(m, c);
    }
    for (int k = tid; k < 1024; k += 256) {
        float fv = d_filt[((size_t)(b*TLEN + f))*NWIN + k];
        s_fk[k] = make_float2(fv, fv);
    }
    __syncthreads();

    if (tid >= 248) return;
    const int j0 = tid*8;
    unsigned long long accp[4] = {0ull, 0ull, 0ull, 0ull};
    const ulonglong2* FK = (const ulonglong2*)s_fk;
    const ulonglong2* EV2 = (const ulonglong2*)s_even + 2*tid;
    const ulonglong2* OD2 = (const ulonglong2*)s_odd + 2*tid;

    unsigned long long A[12], B[12];
    #pragma unroll
    for (int i = 0; i < 6; i++) {
        ulonglong2 va = EV2[i];
        A[2*i] = va.x; A[2*i+1] = va.y;
        ulonglong2 vb = OD2[i];
        B[2*i] = vb.x; B[2*i+1] = vb.y;
    }
    int ldoff = 6;

    #pragma unroll 1
    for (int kc = 0; kc < 1024; kc += 16) {
        const int fk2 = kc >> 1;
        {
            ulonglong2 f0 = FK[fk2+0], f1 = FK[fk2+1], f2 = FK[fk2+2], f3 = FK[fk2+3];
            unsigned long long fkp[8] = {f0.x,f0.y,f1.x,f1.y,f2.x,f2.y,f3.x,f3.y};
            #pragma unroll
            for (int q = 0; q < 8; q += 2) {
                #pragma unroll
                for (int r2 = 0; r2 < 4; r2++) fma2(accp[r2], fkp[q],   A[q/2 + r2]);
                #pragma unroll
                for (int r2 = 0; r2 < 4; r2++) fma2(accp[r2], fkp[q+1], B[q/2 + r2]);
            }
        }
        unsigned long long NA[8], NB[8];
        const bool more = (kc + 16) < 1024;
        if (more) {
            #pragma unroll
            for (int i = 0; i < 4; i++) {
                ulonglong2 va = EV2[ldoff + i];
                NA[2*i] = va.x; NA[2*i+1] = va.y;
                ulonglong2 vb = OD2[ldoff + i];
                NB[2*i] = vb.x; NB[2*i+1] = vb.y;
            }
        }
        {
            ulonglong2 f0 = FK[fk2+4], f1 = FK[fk2+5], f2 = FK[fk2+6], f3 = FK[fk2+7];
            unsigned long long fkp[8] = {f0.x,f0.y,f1.x,f1.y,f2.x,f2.y,f3.x,f3.y};
            #pragma unroll
            for (int q = 0; q < 8; q += 2) {
                #pragma unroll
                for (int r2 = 0; r2 < 4; r2++) fma2(accp[r2], fkp[q],   A[4 + q/2 + r2]);
                #pragma unroll
                for (int r2 = 0; r2 < 4; r2++) fma2(accp[r2], fkp[q+1], B[4 + q/2 + r2]);
            }
        }
        if (more) {
            #pragma unroll
            for (int i = 0; i < 4; i++) { A[i] = A[8+i]; B[i] = B[8+i]; }
            #pragma unroll
            for (int i = 0; i < 8; i++) { A[4+i] = NA[i]; B[4+i] = NB[i]; }
            ldoff += 4;
        }
    }

    float accf[8];
    #pragma unroll
    for (int r2 = 0; r2 < 4; r2++) upk2(accf[2*r2], accf[2*r2+1], accp[r2]);
    const int u0 = f*FRAME + j0;
    #pragma unroll
    for (int r = 0; r < 8; r++) {
        int j = j0 + r, u = u0 + r;
        if (j >= 1 && u < LTOT)
            atomicAdd(out + (size_t)b*LTOT + u, accf[r]);
    }
}

// ---------------- host launcher ----------------
extern "C" void kernel_launch(void* const* d_in, const int* in_sizes, int n_in,
                              void* d_out, int out_size) {
    const float* content  = (const float*)d_in[0];
    const float* f0       = (const float*)d_in[1];
    const float* energy   = (const float*)d_in[2];
    const float* spk      = (const float*)d_in[3];
    const float* source   = (const float*)d_in[4];
    const float* w_content= (const float*)d_in[5];
    const float* b_content= (const float*)d_in[6];
    const float* w_spk    = (const float*)d_in[7];
    const float* b_spk    = (const float*)d_in[8];
    const float* w_f0     = (const float*)d_in[9];
    const float* b_f0     = (const float*)d_in[10];
    const float* w_energy = (const float*)d_in[11];
    const float* b_energy = (const float*)d_in[12];
    const float* dw_w     = (const float*)d_in[13];
    const float* dw_b     = (const float*)d_in[14];
    const float* ln_g     = (const float*)d_in[15];
    const float* ln_b     = (const float*)d_in[16];
    const float* pw1_w    = (const float*)d_in[17];
    const float* pw1_b    = (const float*)d_in[18];
    const float* pw2_w    = (const float*)d_in[19];
    const float* pw2_b    = (const float*)d_in[20];
    const float* out_ln_g = (const float*)d_in[21];
    const float* out_ln_b = (const float*)d_in[22];
    const float* w_out    = (const float*)d_in[23];
    const float* b_out    = (const float*)d_in[24];
    float* out = (float*)d_out;

    __half *w1h, *w2h, *wOh, *h2g, *g2g;
    cudaGetSymbolAddress((void**)&w1h, d_w1h);
    cudaGetSymbolAddress((void**)&w2h, d_w2h);
    cudaGetSymbolAddress((void**)&wOh, d_wOh);
    cudaGetSymbolAddress((void**)&h2g, d_h2);
    cudaGetSymbolAddress((void**)&g2g, d_g2);

    zero_kernel<<<BATCH*LTOT/1024, 256>>>(out);
    cvtall_kernel<<<2*CVT_B1 + NWIN*KOUT/256, 256>>>(pw1_w, pw2_w, w_out);
    spk_kernel<<<BATCH, 512>>>(w_spk, spk, b_content, b_spk, b_f0, b_energy);
    gemm_trunk<<<dim3(CINT/128, TLEN/128, BATCH), 256>>>(w_content, content, f0,
                                                         energy, w_f0, w_energy);
    for (int l = 0; l < 6; l++) {
        dwstats<true><<<dim3(TLEN/8, BATCH), 256>>>(dw_w + (size_t)l*CINT*7,
                                                    dw_b + (size_t)l*CINT,
                                                    ln_g + (size_t)l*CINT,
                                                    ln_b + (size_t)l*CINT);
        gemm5<CINT,0><<<dim3(4, DMLP/128, BATCH), 256>>>(
            h2g, w1h + (size_t)l*DMLP*CINT, pw1_b + (size_t)l*DMLP);
        gemm5<DMLP,1><<<dim3(4, CINT/128, BATCH), 256>>>(
            g2g, w2h + (size_t)l*CINT*DMLP, pw2_b + (size_t)l*CINT);
    }
    dwstats<false><<<dim3(TLEN/8, BATCH), 256>>>(nullptr, nullptr, out_ln_g, out_ln_b);
    gemm5<KOUT,2><<<dim3(4, NWIN/128, BATCH), 256>>>(h2g, wOh, b_out);
    fir5_kernel<<<dim3(TLEN, BATCH), 256>>>(source, out);
}